// round 17
// baseline (speedup 1.0000x reference)
#include <cuda_runtime.h>
#include <cuda_bf16.h>
#include <stdint.h>

#define NN 96
#define DD 64
#define CC 30
#define PREP_BLOCKS 48      // 36 mat + 12 label; then 2 anchors/block for cmask
#define ZERO_BLOCKS 1152    // 4 uniform slab-pairs each
#define DATA_BLOCKS 1152    // (i, 8 slabs) each, uniform 9120 float4

// Scratch (__device__ globals; no allocation allowed)
__device__ float    g_mat[NN * NN];
__device__ unsigned g_smask[NN * 3];
__device__ unsigned g_dmask[NN * 3];
__device__ unsigned g_cmask[NN * NN * 4];   // 96-bit mask per (i,p), stride 4 words
__device__ unsigned g_count;                // prep barrier (monotonic; +48 per launch)

// ---------------------------------------------------------------------------
// K1: 48 prep blocks + 1152 uniform zero blocks (~one wave).
//   Prep section VERBATIM from the passing R7 kernel (bit-identical cmask).
//   Zero blocks: 4 slab-pairs (j1=p, j2=95-p) each -> 4*2328 = 9312 float4,
//   perfectly uniform, hiding all of prep under the 172 MB zero stream.
// ---------------------------------------------------------------------------
__global__ __launch_bounds__(256) void k1_prep_zero(const float* __restrict__ logits,
                                                    const float* __restrict__ labels,
                                                    float4* __restrict__ out) {
    const int tid = threadIdx.x;
    const int bid = blockIdx.x;

    if (bid >= PREP_BLOCKS) {
        // ---------------- zero half: 4 uniform pairs ----------------
        const int zb = bid - PREP_BLOCKS;            // 0..1151
        const float4 z4 = make_float4(0.f, 0.f, 0.f, 0.f);
        #pragma unroll
        for (int t = 0; t < 4; t++) {
            const int pp = zb + ZERO_BLOCKS * t;     // 0..4607
            const int i  = pp / 48;
            const int p  = pp - i * 48;              // 0..47
            const int j1 = p;
            const int j2 = NN - 1 - p;
            const int len1 = (j1 + 1) * 24;
            float4* o1 = out + ((size_t)i * NN + j1) * 2304;
            float4* o2 = out + ((size_t)i * NN + j2) * 2304;
            for (int pos = tid; pos < 2328; pos += 256) {   // len1+len2 = 2328
                int p2 = pos - len1;
                if (p2 < 0) __stcs(o1 + pos, z4);
                else        __stcs(o2 + p2,  z4);
            }
        }
        return;
    }

    // ======================= prep blocks (0..47), verbatim R7 =======================
    __shared__ float    sx[NN * 65];
    __shared__ float    rn[NN];
    __shared__ float    s_rnum[NN], s_rq[NN];
    __shared__ float    s_eps;
    __shared__ float    srow[NN];
    __shared__ unsigned sm[3], dm[3];

    const int warp = tid >> 5, lane = tid & 31;

    if (bid < 36) {
        // ---- mat: one output per thread ----
        #pragma unroll
        for (int it = 0; it < 24; it++) {             // 6144 = 24*256
            int t = it * 256 + tid;
            sx[(t >> 6) * 65 + (t & 63)] = logits[t];
        }
        __syncthreads();
        if (tid < NN) {                               // norms (bit-identical order)
            float s = 0.f;
            #pragma unroll
            for (int d = 0; d < DD; d++) { float v = sx[tid * 65 + d]; s += v * v; }
            rn[tid] = rsqrtf(s);
        }
        __syncthreads();
        const int outp = bid * 256 + tid;             // 0..9215
        const int r = outp / NN;
        const int c = outp - r * NN;
        float acc = 0.f;
        #pragma unroll
        for (int d = 0; d < DD; d++) acc += sx[r * 65 + d] * sx[c * 65 + d];
        g_mat[outp] = -acc * rn[r] * rn[c];
    } else {
        // ---- labels: one warp per row, 8 rows per block ----
        #pragma unroll
        for (int it = 0; it < 12; it++) {             // 2880 = 96*30
            int t = it * 256 + tid;
            if (t < NN * CC) sx[t] = labels[t];
        }
        __syncthreads();
        const int i = (bid - 36) * 8 + warp;          // row 0..95
        #pragma unroll
        for (int wd = 0; wd < 3; wd++) {
            int j = wd * 32 + lane;
            float acc = 0.f;
            #pragma unroll
            for (int cc = 0; cc < CC; cc++) acc += sx[i * CC + cc] * sx[j * CC + cc];
            bool same_raw = acc > 0.f;
            unsigned sb = __ballot_sync(0xffffffffu, same_raw && (j != i));
            unsigned db = __ballot_sync(0xffffffffu, !same_raw);
            if (lane == 0) {
                g_smask[i * 3 + wd] = sb;
                g_dmask[i * 3 + wd] = db;
            }
        }
    }

    // ---- barrier among the 48 prep blocks (wave 1 -> co-resident) ----
    __threadfence();                                  // publish mat / masks
    __syncthreads();
    if (tid == 0) {
        unsigned prev   = atomicAdd(&g_count, 1u);
        unsigned target = (prev / PREP_BLOCKS + 1u) * PREP_BLOCKS;
        while (*(volatile unsigned*)&g_count < target) { }
        __threadfence();                              // acquire
    }
    __syncthreads();

    // ---- epsilon: identical math/order in every block -> deterministic ----
    for (int i = warp; i < NN; i += 8) {
        float S = 0.f, ds = 0.f, ms = 0.f, md = 0.f;
        #pragma unroll
        for (int jj = 0; jj < 3; jj++) {
            float mv = g_mat[i * NN + jj * 32 + lane];
            if ((g_smask[i * 3 + jj] >> lane) & 1u) { S += 1.f; ms += mv; }
            if ((g_dmask[i * 3 + jj] >> lane) & 1u) { ds += 1.f; md += mv; }
        }
        #pragma unroll
        for (int o = 16; o; o >>= 1) {
            S  += __shfl_xor_sync(0xffffffffu, S,  o);
            ds += __shfl_xor_sync(0xffffffffu, ds, o);
            ms += __shfl_xor_sync(0xffffffffu, ms, o);
            md += __shfl_xor_sync(0xffffffffu, md, o);
        }
        if (lane == 0) {
            s_rnum[i] = (S - 1.f) * (S * md - ms * ds);
            s_rq[i]   = 0.5f * S * (S - 1.f) * ds;
        }
    }
    __syncthreads();
    if (tid == 0) {   // serial reduce: identical order every block
        float num = 0.f, q = 0.f;
        for (int i = 0; i < NN; i++) { num += s_rnum[i]; q += s_rq[i]; }
        float mean_delta = num / fmaxf(2.f * q, 1.f);
        s_eps = fmaxf(mean_delta * 0.5f, 0.f);   // relu(mean_delta / K_DELTA)
    }
    __syncthreads();
    const float eps = s_eps;

    // ---- cmask for 2 anchors per block ----
    #pragma unroll
    for (int a0 = 0; a0 < 2; a0++) {
        const int ianc = bid * 2 + a0;
        if (tid < NN) srow[tid] = g_mat[ianc * NN + tid];
        if (tid >= NN && tid < NN + 3) {
            sm[tid - NN] = g_smask[ianc * 3 + (tid - NN)];
            dm[tid - NN] = g_dmask[ianc * 3 + (tid - NN)];
        }
        __syncthreads();
        for (int p = warp; p < NN; p += 8) {
            unsigned sp = (sm[p >> 5] >> (p & 31)) & 1u;
            float matp = srow[p];
            #pragma unroll
            for (int wd = 0; wd < 3; wd++) {
                float m = srow[wd * 32 + lane] - matp;
                bool cc = sp && (((dm[wd] >> lane) & 1u) != 0u) && (m > 0.f) && (m <= eps);
                unsigned b = __ballot_sync(0xffffffffu, cc);
                if (lane == 0) g_cmask[(ianc * NN + p) * 4 + wd] = b;
            }
        }
        __syncthreads();
    }
}

// ---------------------------------------------------------------------------
// K2: data half, 1152 blocks (~one wave). Block = (i, g): slabs
// j in {g, g+12, g+24, g+36} and their mirrors {95-...}. Suffix rows sum to
// exactly 380 rows = 9120 float4 per block -> uniform. Row-i cmask staged
// ONCE per block; inner loop = proven writer loop + one broadcast-group LDS.
// ---------------------------------------------------------------------------
__global__ __launch_bounds__(256) void k2_data(float4* __restrict__ out) {
    __shared__ unsigned scm[NN * 3];     // row-i cmask, scm[k*3+wd]
    const int tid = threadIdx.x;
    const int b   = blockIdx.x;          // 0..1151
    const int i   = b / 12;
    const int g   = b - i * 12;          // 0..11

    for (int t = tid; t < NN * 3; t += 256) {
        int k  = t / 3;
        int wd = t - k * 3;
        scm[t] = g_cmask[((i * NN + k) << 2) + wd];
    }
    __syncthreads();

    const unsigned ONEF = 0x3f800000u;
    #pragma unroll
    for (int s = 0; s < 8; s++) {
        const int j = (s < 4) ? (g + 12 * s) : (NN - 1 - (g + 12 * (s - 4)));
        const int len = (NN - 1 - j) * 24;           // suffix float4 count
        const int j3  = j * 3;
        float4* o = out + ((size_t)i * NN + j) * 2304 + (j + 1) * 24;
        for (int pos = tid; pos < len; pos += 256) {
            int q = pos / 24;
            int r = pos - q * 24;
            int k = j + 1 + q;
            int wd = r >> 3;
            unsigned w = scm[j3 + wd] & scm[k * 3 + wd];
            unsigned bb = w >> ((r & 7) * 4);
            float4 v;
            v.x = __uint_as_float(ONEF & (0u - (bb & 1u)));
            v.y = __uint_as_float(ONEF & (0u - ((bb >> 1) & 1u)));
            v.z = __uint_as_float(ONEF & (0u - ((bb >> 2) & 1u)));
            v.w = __uint_as_float(ONEF & (0u - ((bb >> 3) & 1u)));
            __stcs(o + pos, v);
        }
    }
}

// ---------------------------------------------------------------------------
extern "C" void kernel_launch(void* const* d_in, const int* in_sizes, int n_in,
                              void* d_out, int out_size) {
    const float* logits = (const float*)d_in[0];   // [96,64]
    const float* labels = (const float*)d_in[1];   // [96,30]

    k1_prep_zero<<<PREP_BLOCKS + ZERO_BLOCKS, 256>>>(logits, labels, (float4*)d_out);
    k2_data<<<DATA_BLOCKS, 256>>>((float4*)d_out);
}